// round 14
// baseline (speedup 1.0000x reference)
#include <cuda_runtime.h>
#include <cuda_bf16.h>
#include <cuda_fp16.h>
#include <cstdint>

#define NN 100000
#define EE 3200000
#define IC 500
#define HC 64
#define OC 16
#define NB 98            // scan blocks: 98*1024 >= NN
#define SRC4_CAP 880000  // >= (EE + 3*NN)/4

// ---------------- scratch (device globals; no allocation allowed) ----------------
// All node-indexed propagation tables are stored BY POSITION (degree-sorted).
__device__ float4 g_h0[NN * 4];          // y0 anchor fp32, by position
__device__ uint4  g_y0h[(NN + 1) * 2];   // y0 fp16, by position (+ zero row NN)
__device__ uint4  g_yA[(NN + 1) * 2];    // fp16 ping, by position
__device__ uint4  g_yB[(NN + 1) * 2];    // fp16 pong, by position
__device__ float  g_dinv[NN];            // by original node
__device__ float  g_dinvp[NN];           // by position
__device__ int    g_deg[NN];             // by original node
__device__ int    g_pdeg[NN];            // actual degree, by position
__device__ int2   g_rangep[NN];          // (start, padded end), by position
__device__ int    g_nextp[NN];           // scatter cursor, by position
__device__ int    g_perm[NN];            // node -> position
__device__ int    g_order[NN];           // position -> node
__device__ int4   g_src4[SRC4_CAP];      // CSR src POSITIONS, 4-aligned, pads = NN
__device__ int    g_bsum[128];
__device__ int    g_boff[128];
__device__ int    g_dhist[256];
__device__ int    g_dnext[256];

// ---------------- graph preprocessing ----------------
__global__ void zero_deg_kernel() {
    int i = blockIdx.x * blockDim.x + threadIdx.x;
    if (i < NN) g_deg[i] = 0;
    if (i < 256) g_dhist[i] = 0;
}

__global__ void hist_kernel(const int* __restrict__ col) {
    int e = blockIdx.x * blockDim.x + threadIdx.x;
    if (e < EE) atomicAdd(&g_deg[col[e]], 1);
}

// dinv + degree histogram
__global__ __launch_bounds__(1024) void reduce_kernel() {
    int i = blockIdx.x * blockDim.x + threadIdx.x;
    if (i < NN) {
        int v = g_deg[i];
        g_dinv[i] = rsqrtf((float)(v + 1));  // +1 self-loop
        atomicAdd(&g_dhist[min(v, 255)], 1);
    }
}

// exclusive scan of 256 degree buckets -> g_dnext (bucket base positions)
__global__ void scanb_kernel() {
    int t = threadIdx.x;  // 128 threads, 2 buckets each
    int lane = t & 31, wid = t >> 5;
    int h0 = g_dhist[2 * t];
    int h1 = g_dhist[2 * t + 1];
    int pv = h0 + h1;
    int incl = pv;
#pragma unroll
    for (int off = 1; off < 32; off <<= 1) {
        int n = __shfl_up_sync(0xffffffffu, incl, off);
        if (lane >= off) incl += n;
    }
    __shared__ int ws[4];
    if (lane == 31) ws[wid] = incl;
    __syncthreads();
    int base = 0;
    for (int w = 0; w < wid; w++) base += ws[w];
    int excl = base + incl - pv;
    g_dnext[2 * t] = excl;
    g_dnext[2 * t + 1] = excl + h0;
}

// counting-sort position pop: node -> position; position tables filled
__global__ __launch_bounds__(1024) void perm_kernel() {
    int i = blockIdx.x * blockDim.x + threadIdx.x;
    if (i >= NN) return;
    int v = g_deg[i];
    int pos = atomicAdd(&g_dnext[min(v, 255)], 1);
    g_perm[i] = pos;
    g_order[pos] = i;
    g_dinvp[pos] = g_dinv[i];
    g_pdeg[pos] = v;
}

// block sums of PADDED degrees by position
__global__ __launch_bounds__(1024) void reduce2_kernel() {
    int b = blockIdx.x;
    int t = threadIdx.x;
    int i = b * 1024 + t;
    int v = (i < NN) ? g_pdeg[i] : 0;
    int s = (v + 3) & ~3;
#pragma unroll
    for (int off = 16; off > 0; off >>= 1) s += __shfl_down_sync(0xffffffffu, s, off);
    __shared__ int ws[32];
    int lane = t & 31, wid = t >> 5;
    if (lane == 0) ws[wid] = s;
    __syncthreads();
    if (t < 32) {
        int s2 = ws[t];
#pragma unroll
        for (int off = 16; off > 0; off >>= 1) s2 += __shfl_down_sync(0xffffffffu, s2, off);
        if (t == 0) g_bsum[b] = s2;
    }
}

// scan block sums + zero dummy fp16 rows
__global__ void scanb2_kernel() {
    int t = threadIdx.x;  // 128 threads
    int v = (t < NB) ? g_bsum[t] : 0;
    int lane = t & 31, wid = t >> 5;
    int incl = v;
#pragma unroll
    for (int off = 1; off < 32; off <<= 1) {
        int n = __shfl_up_sync(0xffffffffu, incl, off);
        if (lane >= off) incl += n;
    }
    __shared__ int ws[4];
    if (lane == 31) ws[wid] = incl;
    __syncthreads();
    int base = 0;
    for (int w = 0; w < wid; w++) base += ws[w];
    int excl = base + incl - v;
    if (t < NB) g_boff[t] = excl;
    if (t == 100) {
        uint4 z = make_uint4(0u, 0u, 0u, 0u);
        g_y0h[NN * 2] = z; g_y0h[NN * 2 + 1] = z;
        g_yA[NN * 2]  = z; g_yA[NN * 2 + 1]  = z;
        g_yB[NN * 2]  = z; g_yB[NN * 2 + 1]  = z;
    }
}

// per-position exclusive scan + ranges + cursors + pad fill
__global__ __launch_bounds__(1024) void writeout2_kernel() {
    int b = blockIdx.x;
    int t = threadIdx.x;
    int i = b * 1024 + t;
    int vr = (i < NN) ? g_pdeg[i] : 0;
    int v = (vr + 3) & ~3;
    int lane = t & 31, wid = t >> 5;
    int incl = v;
#pragma unroll
    for (int off = 1; off < 32; off <<= 1) {
        int n = __shfl_up_sync(0xffffffffu, incl, off);
        if (lane >= off) incl += n;
    }
    __shared__ int ws[32];
    if (lane == 31) ws[wid] = incl;
    __syncthreads();
    if (t < 32) {
        int s = ws[t];
#pragma unroll
        for (int off = 1; off < 32; off <<= 1) {
            int n = __shfl_up_sync(0xffffffffu, s, off);
            if (lane >= off) s += n;
        }
        ws[t] = s;
    }
    __syncthreads();
    int warpbase = (wid > 0) ? ws[wid - 1] : 0;
    int excl = g_boff[b] + warpbase + incl - v;
    if (i < NN) {
        g_rangep[i] = make_int2(excl, excl + v);
        g_nextp[i] = excl;
        int* src = (int*)g_src4;
        for (int j = vr; j < v; j++) src[excl + j] = NN;   // pad -> zero row
    }
}

__global__ void scatter_kernel(const int* __restrict__ row,
                               const int* __restrict__ col) {
    int e = blockIdx.x * blockDim.x + threadIdx.x;
    if (e >= EE) return;
    int p  = g_perm[col[e]];
    int sp = g_perm[row[e]];
    int pos = atomicAdd(&g_nextp[p], 1);
    ((int*)g_src4)[pos] = sp;
}

// =====================================================================
// MLP: y0 = dinv .* ( relu(x@W1 + b1) @ W2 + b2 )
// via mma.sync m16n8k16 bf16, split-precision (Ah*Bh + Ah*Bl + Al*Bh)
// Epilogue writes h0/y0h at PERMUTED positions.
// =====================================================================
#define KCH 64
#define AF_HI 0u
#define AF_LO 16384u
#define BF_HI 32768u
#define BF_LO 40960u
#define W2_OFF 49152u
#define B1_OFF 53248u
#define B2_OFF 53504u
#define SMEM_TOT 53568
#define HID_STRIDE 65

__device__ __forceinline__ void split_pack(float a, float b, uint32_t& hi, uint32_t& lo) {
    __nv_bfloat16 ah = __float2bfloat16(a);
    __nv_bfloat16 bh = __float2bfloat16(b);
    __nv_bfloat16 al = __float2bfloat16(a - __bfloat162float(ah));
    __nv_bfloat16 bl = __float2bfloat16(b - __bfloat162float(bh));
    hi = ((uint32_t)__bfloat16_as_ushort(bh) << 16) | __bfloat16_as_ushort(ah);
    lo = ((uint32_t)__bfloat16_as_ushort(bl) << 16) | __bfloat16_as_ushort(al);
}

__device__ __forceinline__ void mma16816(float* c, const uint32_t* a, uint32_t b0, uint32_t b1) {
    asm volatile(
        "mma.sync.aligned.m16n8k16.row.col.f32.bf16.bf16.f32 "
        "{%0,%1,%2,%3}, {%4,%5,%6,%7}, {%8,%9}, {%0,%1,%2,%3};"
        : "+f"(c[0]), "+f"(c[1]), "+f"(c[2]), "+f"(c[3])
        : "r"(a[0]), "r"(a[1]), "r"(a[2]), "r"(a[3]), "r"(b0), "r"(b1));
}

__device__ __forceinline__ uint32_t pack_h2(float a, float b) {
    __half2 h = __floats2half2_rn(a, b);
    return *reinterpret_cast<uint32_t*>(&h);
}

__global__ __launch_bounds__(256, 2)
void mlp_mma_kernel(const float* __restrict__ x,
                    const float* __restrict__ W1,
                    const float* __restrict__ b1,
                    const float* __restrict__ W2,
                    const float* __restrict__ b2) {
    extern __shared__ char smem[];
    int tid = threadIdx.x;
    int wid = tid >> 5;
    int lane = tid & 31;
    int rowBase = blockIdx.x * 128;

    *(float4*)(smem + W2_OFF + tid * 16) = *(const float4*)&W2[tid * 4];
    if (tid < HC) *(float*)(smem + B1_OFF + tid * 4) = b1[tid];
    if (tid < OC) *(float*)(smem + B2_OFF + tid * 4) = b2[tid];

    uint32_t* afh = (uint32_t*)(smem + AF_HI);
    uint32_t* afl = (uint32_t*)(smem + AF_LO);
    uint32_t* bfh = (uint32_t*)(smem + BF_HI);
    uint32_t* bfl = (uint32_t*)(smem + BF_LO);

    float acc[8][4];
#pragma unroll
    for (int nt = 0; nt < 8; nt++)
#pragma unroll
        for (int j = 0; j < 4; j++) acc[nt][j] = 0.f;

    float4 xs[8];
#define LOAD_CHUNK(cc) do {                                                 \
        int kcL = (cc) * KCH;                                               \
        _Pragma("unroll")                                                   \
        for (int i = 0; i < 8; i++) {                                       \
            int idx = i * 256 + tid;                                        \
            int row = idx >> 4;                                             \
            int kq = (idx & 15) * 4;                                        \
            int grow = rowBase + row;                                       \
            int gk = kcL + kq;                                              \
            xs[i] = make_float4(0.f, 0.f, 0.f, 0.f);                        \
            if (grow < NN && gk < IC) xs[i] = *(const float4*)&x[grow * IC + gk]; \
        }                                                                   \
    } while (0)

    LOAD_CHUNK(0);

    for (int c = 0; c < 8; c++) {
        int kc = c * KCH;
        __syncthreads();

#pragma unroll
        for (int i = 0; i < 8; i++) {
            int idx = i * 256 + tid;
            int row = idx >> 4;
            int kq = (idx & 15) * 4;
            float4 xv = xs[i];
            uint32_t h0, l0, h1, l1;
            split_pack(xv.x, xv.y, h0, l0);
            split_pack(xv.z, xv.w, h1, l1);
            int w = row >> 4;
            {
                int kl = kq;
                int s = kl >> 4;
                int ln = ((row & 7) << 2) | ((kl >> 1) & 3);
                int comp = ((kl & 15) >= 8 ? 2 : 0) + ((row & 15) >= 8 ? 1 : 0);
                int off = ((w * 4 + s) * 32 + ln) * 4 + comp;
                afh[off] = h0;
                afl[off] = l0;
            }
            {
                int kl = kq + 2;
                int s = kl >> 4;
                int ln = ((row & 7) << 2) | ((kl >> 1) & 3);
                int comp = ((kl & 15) >= 8 ? 2 : 0) + ((row & 15) >= 8 ? 1 : 0);
                int off = ((w * 4 + s) * 32 + ln) * 4 + comp;
                afh[off] = h1;
                afl[off] = l1;
            }
        }
        if (c < 7) LOAD_CHUNK(c + 1);

        {
            int n = tid & 63;
            int kb = (tid >> 6) * 16;
            int nt = n >> 3;
            int lnbase = (n & 7) << 2;
#pragma unroll
            for (int i = 0; i < 8; i++) {
                int kl = kb + 2 * i;
                int gk0 = kc + kl;
                float w0 = (gk0 < IC) ? W1[gk0 * HC + n] : 0.f;
                float w1 = (gk0 + 1 < IC) ? W1[(gk0 + 1) * HC + n] : 0.f;
                uint32_t h, l;
                split_pack(w0, w1, h, l);
                int s = kl >> 4;
                int ln = lnbase | ((kl >> 1) & 3);
                int comp = (kl & 15) >= 8 ? 1 : 0;
                int off = ((nt * 4 + s) * 32 + ln) * 2 + comp;
                bfh[off] = h;
                bfl[off] = l;
            }
        }
        __syncthreads();

        const uint4* afh4 = (const uint4*)(smem + AF_HI);
        const uint4* afl4 = (const uint4*)(smem + AF_LO);
        const uint2* bfh2 = (const uint2*)(smem + BF_HI);
        const uint2* bfl2 = (const uint2*)(smem + BF_LO);
#pragma unroll
        for (int s = 0; s < 4; s++) {
            uint4 ah4 = afh4[(wid * 4 + s) * 32 + lane];
            uint4 al4 = afl4[(wid * 4 + s) * 32 + lane];
            uint32_t ah[4] = {ah4.x, ah4.y, ah4.z, ah4.w};
            uint32_t al[4] = {al4.x, al4.y, al4.z, al4.w};
#pragma unroll
            for (int nt = 0; nt < 8; nt++) {
                uint2 bh = bfh2[(nt * 4 + s) * 32 + lane];
                uint2 bl = bfl2[(nt * 4 + s) * 32 + lane];
                mma16816(acc[nt], ah, bh.x, bh.y);
                mma16816(acc[nt], ah, bl.x, bl.y);
                mma16816(acc[nt], al, bh.x, bh.y);
            }
        }
    }
#undef LOAD_CHUNK

    __syncthreads();
    {
        float* hid = (float*)smem;
        const float* b1s = (const float*)(smem + B1_OFF);
        int r0 = wid * 16 + (lane >> 2);
        int c0 = (lane & 3) * 2;
#pragma unroll
        for (int nt = 0; nt < 8; nt++) {
            int col = nt * 8 + c0;
            float bcol0 = b1s[col];
            float bcol1 = b1s[col + 1];
            hid[r0 * HID_STRIDE + col]           = fmaxf(acc[nt][0] + bcol0, 0.f);
            hid[r0 * HID_STRIDE + col + 1]       = fmaxf(acc[nt][1] + bcol1, 0.f);
            hid[(r0 + 8) * HID_STRIDE + col]     = fmaxf(acc[nt][2] + bcol0, 0.f);
            hid[(r0 + 8) * HID_STRIDE + col + 1] = fmaxf(acc[nt][3] + bcol1, 0.f);
        }
    }
    __syncthreads();

    if (tid < 128) {
        const float* hid = (const float*)smem;
        const float* b2s = (const float*)(smem + B2_OFF);
        const float4* w2s = (const float4*)(smem + W2_OFF);
        const float* hrow = &hid[tid * HID_STRIDE];

        float4 o0 = make_float4(b2s[0], b2s[1], b2s[2], b2s[3]);
        float4 o1 = make_float4(b2s[4], b2s[5], b2s[6], b2s[7]);
        float4 o2 = make_float4(b2s[8], b2s[9], b2s[10], b2s[11]);
        float4 o3 = make_float4(b2s[12], b2s[13], b2s[14], b2s[15]);
#pragma unroll
        for (int k = 0; k < HC; k++) {
            float h = hrow[k];
            float4 wa = w2s[k * 4 + 0];
            float4 wb = w2s[k * 4 + 1];
            float4 wc = w2s[k * 4 + 2];
            float4 wd = w2s[k * 4 + 3];
            o0.x = fmaf(h, wa.x, o0.x); o0.y = fmaf(h, wa.y, o0.y);
            o0.z = fmaf(h, wa.z, o0.z); o0.w = fmaf(h, wa.w, o0.w);
            o1.x = fmaf(h, wb.x, o1.x); o1.y = fmaf(h, wb.y, o1.y);
            o1.z = fmaf(h, wb.z, o1.z); o1.w = fmaf(h, wb.w, o1.w);
            o2.x = fmaf(h, wc.x, o2.x); o2.y = fmaf(h, wc.y, o2.y);
            o2.z = fmaf(h, wc.z, o2.z); o2.w = fmaf(h, wc.w, o2.w);
            o3.x = fmaf(h, wd.x, o3.x); o3.y = fmaf(h, wd.y, o3.y);
            o3.z = fmaf(h, wd.z, o3.z); o3.w = fmaf(h, wd.w, o3.w);
        }
        int grow = rowBase + tid;
        if (grow < NN) {
            float di = g_dinv[grow];   // y0 = dinv * h0
            o0.x *= di; o0.y *= di; o0.z *= di; o0.w *= di;
            o1.x *= di; o1.y *= di; o1.z *= di; o1.w *= di;
            o2.x *= di; o2.y *= di; o2.z *= di; o2.w *= di;
            o3.x *= di; o3.y *= di; o3.z *= di; o3.w *= di;
            int p = g_perm[grow];      // store at PERMUTED position
            g_h0[p * 4 + 0] = o0;
            g_h0[p * 4 + 1] = o1;
            g_h0[p * 4 + 2] = o2;
            g_h0[p * 4 + 3] = o3;
            uint4 p0, p1;
            p0.x = pack_h2(o0.x, o0.y); p0.y = pack_h2(o0.z, o0.w);
            p0.z = pack_h2(o1.x, o1.y); p0.w = pack_h2(o1.z, o1.w);
            p1.x = pack_h2(o2.x, o2.y); p1.y = pack_h2(o2.z, o2.w);
            p1.z = pack_h2(o3.x, o3.y); p1.w = pack_h2(o3.z, o3.w);
            g_y0h[p * 2 + 0] = p0;
            g_y0h[p * 2 + 1] = p1;
        }
    }
}

// ---------------- APPNP propagation: position-ordered (degree-sorted + coalesced) ----------------
__global__ __launch_bounds__(256) void prop_kernel(int insel, int outsel,
                                                   float4* __restrict__ dout) {
    const uint4* yin = (insel == 0) ? g_y0h : ((insel == 1) ? g_yA : g_yB);
    uint4* yout = (outsel == 1) ? g_yA : g_yB;
    bool final_step = (outsel == 3);

    int t = blockIdx.x * blockDim.x + threadIdx.x;
    int p = t >> 1;                  // POSITION (degree-sorted)
    if (p >= NN) return;
    int hf = t & 1;

    int2 rng = g_rangep[p];
    int start = rng.x;
    int end = rng.y;

    float a0 = 0.f, a1 = 0.f, a2 = 0.f, a3 = 0.f;
    float a4 = 0.f, a5 = 0.f, a6 = 0.f, a7 = 0.f;

#define GATHER(id) do {                                              \
        uint4 v = yin[(id) * 2 + hf];                                \
        float2 f0 = __half22float2(*reinterpret_cast<__half2*>(&v.x)); \
        float2 f1 = __half22float2(*reinterpret_cast<__half2*>(&v.y)); \
        float2 f2 = __half22float2(*reinterpret_cast<__half2*>(&v.z)); \
        float2 f3 = __half22float2(*reinterpret_cast<__half2*>(&v.w)); \
        a0 += f0.x; a1 += f0.y; a2 += f1.x; a3 += f1.y;              \
        a4 += f2.x; a5 += f2.y; a6 += f3.x; a7 += f3.y;              \
    } while (0)

    for (int e = start; e < end; e += 4) {
        int4 ids = g_src4[e >> 2];
        GATHER(ids.x);
        GATHER(ids.y);
        GATHER(ids.z);
        GATHER(ids.w);
    }
#undef GATHER

    // self term
    {
        uint4 s = yin[p * 2 + hf];
        float2 s0 = __half22float2(*reinterpret_cast<__half2*>(&s.x));
        float2 s1 = __half22float2(*reinterpret_cast<__half2*>(&s.y));
        float2 s2 = __half22float2(*reinterpret_cast<__half2*>(&s.z));
        float2 s3 = __half22float2(*reinterpret_cast<__half2*>(&s.w));
        a0 += s0.x; a1 += s0.y; a2 += s1.x; a3 += s1.y;
        a4 += s2.x; a5 += s2.y; a6 += s3.x; a7 += s3.y;
    }

    float di = g_dinvp[p];
    float4 y0a = g_h0[p * 4 + hf * 2];
    float4 y0b = g_h0[p * 4 + hf * 2 + 1];
    if (!final_step) {
        float d2 = 0.9f * di * di;
        float o0 = d2 * a0 + 0.1f * y0a.x;
        float o1 = d2 * a1 + 0.1f * y0a.y;
        float o2 = d2 * a2 + 0.1f * y0a.z;
        float o3 = d2 * a3 + 0.1f * y0a.w;
        float o4 = d2 * a4 + 0.1f * y0b.x;
        float o5 = d2 * a5 + 0.1f * y0b.y;
        float o6 = d2 * a6 + 0.1f * y0b.z;
        float o7 = d2 * a7 + 0.1f * y0b.w;
        uint4 pk;
        pk.x = pack_h2(o0, o1); pk.y = pack_h2(o2, o3);
        pk.z = pack_h2(o4, o5); pk.w = pack_h2(o6, o7);
        yout[p * 2 + hf] = pk;
    } else {
        float dm = 0.9f * di;
        float inv = 0.1f / di;
        float4 oa, ob;
        oa.x = dm * a0 + inv * y0a.x;
        oa.y = dm * a1 + inv * y0a.y;
        oa.z = dm * a2 + inv * y0a.z;
        oa.w = dm * a3 + inv * y0a.w;
        ob.x = dm * a4 + inv * y0b.x;
        ob.y = dm * a5 + inv * y0b.y;
        ob.z = dm * a6 + inv * y0b.z;
        ob.w = dm * a7 + inv * y0b.w;
        int orig = g_order[p];           // scatter only on final step
        dout[orig * 4 + hf * 2] = oa;
        dout[orig * 4 + hf * 2 + 1] = ob;
    }
}

// ---------------- launch ----------------
extern "C" void kernel_launch(void* const* d_in, const int* in_sizes, int n_in,
                              void* d_out, int out_size) {
    const float* x  = (const float*)d_in[0];
    const int* ei   = (const int*)d_in[1];   // int32 (JAX x64-disabled)
    const float* W1 = (const float*)d_in[2];
    const float* b1 = (const float*)d_in[3];
    const float* W2 = (const float*)d_in[4];
    const float* b2 = (const float*)d_in[5];
    float4* out = (float4*)d_out;

    const int* row = ei;        // sources
    const int* col = ei + EE;   // targets

    zero_deg_kernel<<<(NN + 255) / 256, 256>>>();
    hist_kernel<<<(EE + 255) / 256, 256>>>(col);
    reduce_kernel<<<NB, 1024>>>();           // dinv + degree histogram
    scanb_kernel<<<1, 128>>>();              // bucket scan
    perm_kernel<<<NB, 1024>>>();             // node->position + position tables
    cudaFuncSetAttribute(mlp_mma_kernel, cudaFuncAttributeMaxDynamicSharedMemorySize, SMEM_TOT);
    mlp_mma_kernel<<<(NN + 127) / 128, 256, SMEM_TOT>>>(x, W1, b1, W2, b2);  // slot 6 (profiler window)
    reduce2_kernel<<<NB, 1024>>>();          // padded-degree block sums (by position)
    scanb2_kernel<<<1, 128>>>();             // block-sum scan + zero dummy rows
    writeout2_kernel<<<NB, 1024>>>();        // ranges + cursors + pad fill
    scatter_kernel<<<(EE + 255) / 256, 256>>>(row, col);

    int insel = 0;
    for (int k = 0; k < 10; k++) {
        int outsel = (k == 9) ? 3 : ((k & 1) ? 2 : 1);
        prop_kernel<<<(NN * 2 + 255) / 256, 256>>>(insel, outsel, out);
        insel = outsel;
    }
}

// round 15
// speedup vs baseline: 1.2698x; 1.2698x over previous
#include <cuda_runtime.h>
#include <cuda_bf16.h>
#include <cuda_fp16.h>
#include <cstdint>

#define NN 100000
#define EE 3200000
#define IC 500
#define HC 64
#define OC 16
#define NB 98            // scan blocks: 98*1024 >= NN
#define SRC4_CAP 880000  // >= (EE + 3*NN)/4

// ---------------- scratch (device globals; no allocation allowed) ----------------
__device__ float4 g_h0[NN * 4];          // y0 = dinv .* h0  (fp32 anchor, exact)
__device__ uint4  g_y0h[(NN + 1) * 2];   // y0 fp16 table (+ zero row NN)
__device__ uint4  g_yA[(NN + 1) * 2];    // fp16 ping
__device__ uint4  g_yB[(NN + 1) * 2];    // fp16 pong
__device__ float  g_dinv[NN];
__device__ int    g_deg[NN];
__device__ int    g_rowptr[NN + 1];      // padded (deg rounded up to 4)
__device__ int    g_next[NN];
__device__ int4   g_src4[SRC4_CAP];      // CSR src ids, 4-aligned rows, pads = NN
__device__ int    g_bsum[128];
__device__ int    g_boff[128];

// ---------------- graph preprocessing ----------------
__global__ void zero_deg_kernel() {
    int i = blockIdx.x * blockDim.x + threadIdx.x;
    if (i < NN) g_deg[i] = 0;
}

__global__ void hist_kernel(const int* __restrict__ col) {
    int e = blockIdx.x * blockDim.x + threadIdx.x;
    if (e < EE) atomicAdd(&g_deg[col[e]], 1);
}

// pass 1 of scan (over PADDED degrees) + dinv computation
__global__ __launch_bounds__(1024) void reduce_kernel() {
    int b = blockIdx.x;
    int t = threadIdx.x;
    int i = b * 1024 + t;
    int v = (i < NN) ? g_deg[i] : 0;
    if (i < NN) g_dinv[i] = rsqrtf((float)(v + 1));  // +1 self-loop
    int s = (v + 3) & ~3;                             // padded degree
#pragma unroll
    for (int off = 16; off > 0; off >>= 1) s += __shfl_down_sync(0xffffffffu, s, off);
    __shared__ int ws[32];
    int lane = t & 31, wid = t >> 5;
    if (lane == 0) ws[wid] = s;
    __syncthreads();
    if (t < 32) {
        int s2 = ws[t];
#pragma unroll
        for (int off = 16; off > 0; off >>= 1) s2 += __shfl_down_sync(0xffffffffu, s2, off);
        if (t == 0) g_bsum[b] = s2;
    }
}

__global__ void scanb_kernel() {
    int t = threadIdx.x;  // 128 threads
    int v = (t < NB) ? g_bsum[t] : 0;
    int lane = t & 31, wid = t >> 5;
    int incl = v;
#pragma unroll
    for (int off = 1; off < 32; off <<= 1) {
        int n = __shfl_up_sync(0xffffffffu, incl, off);
        if (lane >= off) incl += n;
    }
    __shared__ int ws[4];
    if (lane == 31) ws[wid] = incl;
    __syncthreads();
    int base = 0;
    for (int w = 0; w < wid; w++) base += ws[w];
    int excl = base + incl - v;
    if (t < NB) g_boff[t] = excl;
    if (t == NB - 1) g_rowptr[NN] = excl + v;
    // zero the dummy row NN of all fp16 tables (pads gather from here)
    if (t == 100) {
        uint4 z = make_uint4(0u, 0u, 0u, 0u);
        g_y0h[NN * 2] = z; g_y0h[NN * 2 + 1] = z;
        g_yA[NN * 2]  = z; g_yA[NN * 2 + 1]  = z;
        g_yB[NN * 2]  = z; g_yB[NN * 2 + 1]  = z;
    }
}

__global__ __launch_bounds__(1024) void writeout_kernel() {
    int b = blockIdx.x;
    int t = threadIdx.x;
    int i = b * 1024 + t;
    int vr = (i < NN) ? g_deg[i] : 0;
    int v = (vr + 3) & ~3;                 // padded degree
    int lane = t & 31, wid = t >> 5;
    int incl = v;
#pragma unroll
    for (int off = 1; off < 32; off <<= 1) {
        int n = __shfl_up_sync(0xffffffffu, incl, off);
        if (lane >= off) incl += n;
    }
    __shared__ int ws[32];
    if (lane == 31) ws[wid] = incl;
    __syncthreads();
    if (t < 32) {
        int s = ws[t];
#pragma unroll
        for (int off = 1; off < 32; off <<= 1) {
            int n = __shfl_up_sync(0xffffffffu, s, off);
            if (lane >= off) s += n;
        }
        ws[t] = s;
    }
    __syncthreads();
    int warpbase = (wid > 0) ? ws[wid - 1] : 0;
    int excl = g_boff[b] + warpbase + incl - v;
    if (i < NN) {
        g_rowptr[i] = excl;
        g_next[i] = excl;
        int* src = (int*)g_src4;
        for (int j = vr; j < v; j++) src[excl + j] = NN;   // pad slots
    }
}

__global__ void scatter_kernel(const int* __restrict__ row,
                               const int* __restrict__ col) {
    int e = blockIdx.x * blockDim.x + threadIdx.x;
    if (e >= EE) return;
    int c = col[e];
    int pos = atomicAdd(&g_next[c], 1);
    ((int*)g_src4)[pos] = row[e];
}

// =====================================================================
// MLP: y0 = dinv .* ( relu(x@W1 + b1) @ W2 + b2 )
// via mma.sync m16n8k16 FP16, split-precision on A only:
//   A = Ah + Al (two fp16 terms, ~21 mantissa bits), B = fp16(W1)
//   D = Ah*B + Al*B   (2 products per k-step instead of 3)
// x staging register-pipelined (chunk c+1 prefetched during chunk c MMAs).
// =====================================================================
#define KCH 64
#define AF_HI 0u
#define AF_LO 16384u
#define BF_HI 32768u
#define W2_OFF 49152u
#define B1_OFF 53248u
#define B2_OFF 53504u
#define SMEM_TOT 53568
#define HID_STRIDE 65

__device__ __forceinline__ void split_pack_a(float a, float b, uint32_t& hi, uint32_t& lo) {
    __half ah = __float2half_rn(a);
    __half bh = __float2half_rn(b);
    __half al = __float2half_rn(a - __half2float(ah));
    __half bl = __float2half_rn(b - __half2float(bh));
    hi = ((uint32_t)__half_as_ushort(bh) << 16) | __half_as_ushort(ah);
    lo = ((uint32_t)__half_as_ushort(bl) << 16) | __half_as_ushort(al);
}

__device__ __forceinline__ uint32_t pack_h2(float a, float b) {
    __half2 h = __floats2half2_rn(a, b);
    return *reinterpret_cast<uint32_t*>(&h);
}

__device__ __forceinline__ void mma16816(float* c, const uint32_t* a, uint32_t b0, uint32_t b1) {
    asm volatile(
        "mma.sync.aligned.m16n8k16.row.col.f32.f16.f16.f32 "
        "{%0,%1,%2,%3}, {%4,%5,%6,%7}, {%8,%9}, {%0,%1,%2,%3};"
        : "+f"(c[0]), "+f"(c[1]), "+f"(c[2]), "+f"(c[3])
        : "r"(a[0]), "r"(a[1]), "r"(a[2]), "r"(a[3]), "r"(b0), "r"(b1));
}

__global__ __launch_bounds__(256, 2)
void mlp_mma_kernel(const float* __restrict__ x,
                    const float* __restrict__ W1,
                    const float* __restrict__ b1,
                    const float* __restrict__ W2,
                    const float* __restrict__ b2) {
    extern __shared__ char smem[];
    int tid = threadIdx.x;
    int wid = tid >> 5;
    int lane = tid & 31;
    int rowBase = blockIdx.x * 128;

    *(float4*)(smem + W2_OFF + tid * 16) = *(const float4*)&W2[tid * 4];
    if (tid < HC) *(float*)(smem + B1_OFF + tid * 4) = b1[tid];
    if (tid < OC) *(float*)(smem + B2_OFF + tid * 4) = b2[tid];

    uint32_t* afh = (uint32_t*)(smem + AF_HI);
    uint32_t* afl = (uint32_t*)(smem + AF_LO);
    uint32_t* bfh = (uint32_t*)(smem + BF_HI);

    float acc[8][4];
#pragma unroll
    for (int nt = 0; nt < 8; nt++)
#pragma unroll
        for (int j = 0; j < 4; j++) acc[nt][j] = 0.f;

    float4 xs[8];
#define LOAD_CHUNK(cc) do {                                                 \
        int kcL = (cc) * KCH;                                               \
        _Pragma("unroll")                                                   \
        for (int i = 0; i < 8; i++) {                                       \
            int idx = i * 256 + tid;                                        \
            int row = idx >> 4;                                             \
            int kq = (idx & 15) * 4;                                        \
            int grow = rowBase + row;                                       \
            int gk = kcL + kq;                                              \
            xs[i] = make_float4(0.f, 0.f, 0.f, 0.f);                        \
            if (grow < NN && gk < IC) xs[i] = *(const float4*)&x[grow * IC + gk]; \
        }                                                                   \
    } while (0)

    LOAD_CHUNK(0);

    for (int c = 0; c < 8; c++) {
        int kc = c * KCH;
        __syncthreads();

        // ---- stage A from registers (fp16 hi/lo, frag layout) ----
#pragma unroll
        for (int i = 0; i < 8; i++) {
            int idx = i * 256 + tid;
            int row = idx >> 4;
            int kq = (idx & 15) * 4;
            float4 xv = xs[i];
            uint32_t h0, l0, h1, l1;
            split_pack_a(xv.x, xv.y, h0, l0);
            split_pack_a(xv.z, xv.w, h1, l1);
            int w = row >> 4;
            {
                int kl = kq;
                int s = kl >> 4;
                int ln = ((row & 7) << 2) | ((kl >> 1) & 3);
                int comp = ((kl & 15) >= 8 ? 2 : 0) + ((row & 15) >= 8 ? 1 : 0);
                int off = ((w * 4 + s) * 32 + ln) * 4 + comp;
                afh[off] = h0;
                afl[off] = l0;
            }
            {
                int kl = kq + 2;
                int s = kl >> 4;
                int ln = ((row & 7) << 2) | ((kl >> 1) & 3);
                int comp = ((kl & 15) >= 8 ? 2 : 0) + ((row & 15) >= 8 ? 1 : 0);
                int off = ((w * 4 + s) * 32 + ln) * 4 + comp;
                afh[off] = h1;
                afl[off] = l1;
            }
        }
        if (c < 7) LOAD_CHUNK(c + 1);

        // ---- stage B: fp16(W1^T), single table ----
        {
            int n = tid & 63;
            int kb = (tid >> 6) * 16;
            int nt = n >> 3;
            int lnbase = (n & 7) << 2;
#pragma unroll
            for (int i = 0; i < 8; i++) {
                int kl = kb + 2 * i;
                int gk0 = kc + kl;
                float w0 = (gk0 < IC) ? W1[gk0 * HC + n] : 0.f;
                float w1 = (gk0 + 1 < IC) ? W1[(gk0 + 1) * HC + n] : 0.f;
                uint32_t h = pack_h2(w0, w1);
                int s = kl >> 4;
                int ln = lnbase | ((kl >> 1) & 3);
                int comp = (kl & 15) >= 8 ? 1 : 0;
                int off = ((nt * 4 + s) * 32 + ln) * 2 + comp;
                bfh[off] = h;
            }
        }
        __syncthreads();

        const uint4* afh4 = (const uint4*)(smem + AF_HI);
        const uint4* afl4 = (const uint4*)(smem + AF_LO);
        const uint2* bfh2 = (const uint2*)(smem + BF_HI);
#pragma unroll
        for (int s = 0; s < 4; s++) {
            uint4 ah4 = afh4[(wid * 4 + s) * 32 + lane];
            uint4 al4 = afl4[(wid * 4 + s) * 32 + lane];
            uint32_t ah[4] = {ah4.x, ah4.y, ah4.z, ah4.w};
            uint32_t al[4] = {al4.x, al4.y, al4.z, al4.w};
#pragma unroll
            for (int nt = 0; nt < 8; nt++) {
                uint2 bh = bfh2[(nt * 4 + s) * 32 + lane];
                mma16816(acc[nt], ah, bh.x, bh.y);
                mma16816(acc[nt], al, bh.x, bh.y);
            }
        }
    }
#undef LOAD_CHUNK

    __syncthreads();
    {
        float* hid = (float*)smem;
        const float* b1s = (const float*)(smem + B1_OFF);
        int r0 = wid * 16 + (lane >> 2);
        int c0 = (lane & 3) * 2;
#pragma unroll
        for (int nt = 0; nt < 8; nt++) {
            int col = nt * 8 + c0;
            float bcol0 = b1s[col];
            float bcol1 = b1s[col + 1];
            hid[r0 * HID_STRIDE + col]           = fmaxf(acc[nt][0] + bcol0, 0.f);
            hid[r0 * HID_STRIDE + col + 1]       = fmaxf(acc[nt][1] + bcol1, 0.f);
            hid[(r0 + 8) * HID_STRIDE + col]     = fmaxf(acc[nt][2] + bcol0, 0.f);
            hid[(r0 + 8) * HID_STRIDE + col + 1] = fmaxf(acc[nt][3] + bcol1, 0.f);
        }
    }
    __syncthreads();

    if (tid < 128) {
        const float* hid = (const float*)smem;
        const float* b2s = (const float*)(smem + B2_OFF);
        const float4* w2s = (const float4*)(smem + W2_OFF);
        const float* hrow = &hid[tid * HID_STRIDE];

        float4 o0 = make_float4(b2s[0], b2s[1], b2s[2], b2s[3]);
        float4 o1 = make_float4(b2s[4], b2s[5], b2s[6], b2s[7]);
        float4 o2 = make_float4(b2s[8], b2s[9], b2s[10], b2s[11]);
        float4 o3 = make_float4(b2s[12], b2s[13], b2s[14], b2s[15]);
#pragma unroll
        for (int k = 0; k < HC; k++) {
            float h = hrow[k];
            float4 wa = w2s[k * 4 + 0];
            float4 wb = w2s[k * 4 + 1];
            float4 wc = w2s[k * 4 + 2];
            float4 wd = w2s[k * 4 + 3];
            o0.x = fmaf(h, wa.x, o0.x); o0.y = fmaf(h, wa.y, o0.y);
            o0.z = fmaf(h, wa.z, o0.z); o0.w = fmaf(h, wa.w, o0.w);
            o1.x = fmaf(h, wb.x, o1.x); o1.y = fmaf(h, wb.y, o1.y);
            o1.z = fmaf(h, wb.z, o1.z); o1.w = fmaf(h, wb.w, o1.w);
            o2.x = fmaf(h, wc.x, o2.x); o2.y = fmaf(h, wc.y, o2.y);
            o2.z = fmaf(h, wc.z, o2.z); o2.w = fmaf(h, wc.w, o2.w);
            o3.x = fmaf(h, wd.x, o3.x); o3.y = fmaf(h, wd.y, o3.y);
            o3.z = fmaf(h, wd.z, o3.z); o3.w = fmaf(h, wd.w, o3.w);
        }
        int grow = rowBase + tid;
        if (grow < NN) {
            float di = g_dinv[grow];   // y0 = dinv * h0
            o0.x *= di; o0.y *= di; o0.z *= di; o0.w *= di;
            o1.x *= di; o1.y *= di; o1.z *= di; o1.w *= di;
            o2.x *= di; o2.y *= di; o2.z *= di; o2.w *= di;
            o3.x *= di; o3.y *= di; o3.z *= di; o3.w *= di;
            g_h0[grow * 4 + 0] = o0;
            g_h0[grow * 4 + 1] = o1;
            g_h0[grow * 4 + 2] = o2;
            g_h0[grow * 4 + 3] = o3;
            uint4 p0, p1;
            p0.x = pack_h2(o0.x, o0.y); p0.y = pack_h2(o0.z, o0.w);
            p0.z = pack_h2(o1.x, o1.y); p0.w = pack_h2(o1.z, o1.w);
            p1.x = pack_h2(o2.x, o2.y); p1.y = pack_h2(o2.z, o2.w);
            p1.z = pack_h2(o3.x, o3.y); p1.w = pack_h2(o3.z, o3.w);
            g_y0h[grow * 2 + 0] = p0;
            g_y0h[grow * 2 + 1] = p1;
        }
    }
}

// ---------------- APPNP propagation: 2 lanes per node, zero shuffles ----------------
// intermediate: y_{k+1} = 0.9*dinv^2*(sum_in y + y_self) + 0.1*y0   (fp16 store)
// final:        out     = 0.9*dinv  *(sum_in y + y_self) + 0.1*y0/dinv (fp32)
__global__ __launch_bounds__(256) void prop_kernel(int insel, int outsel,
                                                   float4* __restrict__ dout) {
    const uint4* yin = (insel == 0) ? g_y0h : ((insel == 1) ? g_yA : g_yB);
    uint4* yout = (outsel == 1) ? g_yA : g_yB;
    bool final_step = (outsel == 3);

    int t = blockIdx.x * blockDim.x + threadIdx.x;
    int node = t >> 1;
    if (node >= NN) return;
    int hf = t & 1;                  // 16B half of the 32B fp16 row

    int start = g_rowptr[node];
    int end = g_rowptr[node + 1];    // padded: (end-start) % 4 == 0

    float a0 = 0.f, a1 = 0.f, a2 = 0.f, a3 = 0.f;
    float a4 = 0.f, a5 = 0.f, a6 = 0.f, a7 = 0.f;

#define GATHER(id) do {                                              \
        uint4 v = yin[(id) * 2 + hf];                                \
        float2 f0 = __half22float2(*reinterpret_cast<__half2*>(&v.x)); \
        float2 f1 = __half22float2(*reinterpret_cast<__half2*>(&v.y)); \
        float2 f2 = __half22float2(*reinterpret_cast<__half2*>(&v.z)); \
        float2 f3 = __half22float2(*reinterpret_cast<__half2*>(&v.w)); \
        a0 += f0.x; a1 += f0.y; a2 += f1.x; a3 += f1.y;              \
        a4 += f2.x; a5 += f2.y; a6 += f3.x; a7 += f3.y;              \
    } while (0)

    for (int e = start; e < end; e += 4) {
        int4 ids = g_src4[e >> 2];    // broadcast within the lane pair
        GATHER(ids.x);
        GATHER(ids.y);
        GATHER(ids.z);
        GATHER(ids.w);
    }
#undef GATHER

    // self term (fp16 table)
    {
        uint4 s = yin[node * 2 + hf];
        float2 s0 = __half22float2(*reinterpret_cast<__half2*>(&s.x));
        float2 s1 = __half22float2(*reinterpret_cast<__half2*>(&s.y));
        float2 s2 = __half22float2(*reinterpret_cast<__half2*>(&s.z));
        float2 s3 = __half22float2(*reinterpret_cast<__half2*>(&s.w));
        a0 += s0.x; a1 += s0.y; a2 += s1.x; a3 += s1.y;
        a4 += s2.x; a5 += s2.y; a6 += s3.x; a7 += s3.y;
    }

    float di = g_dinv[node];
    float4 y0a = g_h0[node * 4 + hf * 2];      // fp32 anchor
    float4 y0b = g_h0[node * 4 + hf * 2 + 1];
    if (!final_step) {
        float d2 = 0.9f * di * di;
        float o0 = d2 * a0 + 0.1f * y0a.x;
        float o1 = d2 * a1 + 0.1f * y0a.y;
        float o2 = d2 * a2 + 0.1f * y0a.z;
        float o3 = d2 * a3 + 0.1f * y0a.w;
        float o4 = d2 * a4 + 0.1f * y0b.x;
        float o5 = d2 * a5 + 0.1f * y0b.y;
        float o6 = d2 * a6 + 0.1f * y0b.z;
        float o7 = d2 * a7 + 0.1f * y0b.w;
        uint4 p;
        p.x = pack_h2(o0, o1); p.y = pack_h2(o2, o3);
        p.z = pack_h2(o4, o5); p.w = pack_h2(o6, o7);
        yout[node * 2 + hf] = p;
    } else {
        float dm = 0.9f * di;
        float inv = 0.1f / di;
        float4 oa, ob;
        oa.x = dm * a0 + inv * y0a.x;
        oa.y = dm * a1 + inv * y0a.y;
        oa.z = dm * a2 + inv * y0a.z;
        oa.w = dm * a3 + inv * y0a.w;
        ob.x = dm * a4 + inv * y0b.x;
        ob.y = dm * a5 + inv * y0b.y;
        ob.z = dm * a6 + inv * y0b.z;
        ob.w = dm * a7 + inv * y0b.w;
        dout[node * 4 + hf * 2] = oa;
        dout[node * 4 + hf * 2 + 1] = ob;
    }
}

// ---------------- launch ----------------
extern "C" void kernel_launch(void* const* d_in, const int* in_sizes, int n_in,
                              void* d_out, int out_size) {
    const float* x  = (const float*)d_in[0];
    const int* ei   = (const int*)d_in[1];   // int32 (JAX x64-disabled)
    const float* W1 = (const float*)d_in[2];
    const float* b1 = (const float*)d_in[3];
    const float* W2 = (const float*)d_in[4];
    const float* b2 = (const float*)d_in[5];
    float4* out = (float4*)d_out;

    const int* row = ei;        // sources
    const int* col = ei + EE;   // targets

    zero_deg_kernel<<<(NN + 255) / 256, 256>>>();
    hist_kernel<<<(EE + 255) / 256, 256>>>(col);
    reduce_kernel<<<NB, 1024>>>();           // dinv + padded-degree partial sums
    scanb_kernel<<<1, 128>>>();              // + zero dummy rows
    writeout_kernel<<<NB, 1024>>>();         // rowptr/next + pad fill
    scatter_kernel<<<(EE + 255) / 256, 256>>>(row, col);

    cudaFuncSetAttribute(mlp_mma_kernel, cudaFuncAttributeMaxDynamicSharedMemorySize, SMEM_TOT);
    mlp_mma_kernel<<<(NN + 127) / 128, 256, SMEM_TOT>>>(x, W1, b1, W2, b2);

    int insel = 0;
    for (int k = 0; k < 10; k++) {
        int outsel = (k == 9) ? 3 : ((k & 1) ? 2 : 1);
        prop_kernel<<<(NN * 2 + 255) / 256, 256>>>(insel, outsel, out);
        insel = outsel;
    }
}

// round 16
// speedup vs baseline: 1.3288x; 1.0465x over previous
#include <cuda_runtime.h>
#include <cuda_bf16.h>
#include <cuda_fp16.h>
#include <cstdint>

#define NN 100000
#define EE 3200000
#define IC 500
#define HC 64
#define OC 16
#define NB 98            // scan blocks: 98*1024 >= NN
#define SRC4_CAP 880000  // >= (EE + 3*NN)/4

// ---------------- scratch (device globals; no allocation allowed) ----------------
__device__ float4 g_h0[NN * 4];          // y0 = dinv .* h0  (fp32 anchor, exact)
__device__ uint4  g_y0h[(NN + 1) * 2];   // y0 fp16 table (+ zero row NN)
__device__ uint4  g_yA[(NN + 1) * 2];    // fp16 ping
__device__ uint4  g_yB[(NN + 1) * 2];    // fp16 pong
__device__ float  g_dinv[NN];
__device__ int    g_deg[NN];
__device__ int    g_rowptr[NN + 1];      // padded (deg rounded up to 4)
__device__ int    g_next[NN];
__device__ int4   g_src4[SRC4_CAP];      // CSR src ids, 4-aligned rows, pads = NN
__device__ int    g_bsum[128];
__device__ int    g_boff[128];

// ---------------- graph preprocessing ----------------
__global__ void zero_deg_kernel() {
    int i = blockIdx.x * blockDim.x + threadIdx.x;
    if (i < NN) g_deg[i] = 0;
}

__global__ void hist_kernel(const int* __restrict__ col) {
    int e = blockIdx.x * blockDim.x + threadIdx.x;
    if (e < EE) atomicAdd(&g_deg[col[e]], 1);
}

// pass 1 of scan (over PADDED degrees) + dinv computation
__global__ __launch_bounds__(1024) void reduce_kernel() {
    int b = blockIdx.x;
    int t = threadIdx.x;
    int i = b * 1024 + t;
    int v = (i < NN) ? g_deg[i] : 0;
    if (i < NN) g_dinv[i] = rsqrtf((float)(v + 1));  // +1 self-loop
    int s = (v + 3) & ~3;                             // padded degree
#pragma unroll
    for (int off = 16; off > 0; off >>= 1) s += __shfl_down_sync(0xffffffffu, s, off);
    __shared__ int ws[32];
    int lane = t & 31, wid = t >> 5;
    if (lane == 0) ws[wid] = s;
    __syncthreads();
    if (t < 32) {
        int s2 = ws[t];
#pragma unroll
        for (int off = 16; off > 0; off >>= 1) s2 += __shfl_down_sync(0xffffffffu, s2, off);
        if (t == 0) g_bsum[b] = s2;
    }
}

__global__ void scanb_kernel() {
    int t = threadIdx.x;  // 128 threads
    int v = (t < NB) ? g_bsum[t] : 0;
    int lane = t & 31, wid = t >> 5;
    int incl = v;
#pragma unroll
    for (int off = 1; off < 32; off <<= 1) {
        int n = __shfl_up_sync(0xffffffffu, incl, off);
        if (lane >= off) incl += n;
    }
    __shared__ int ws[4];
    if (lane == 31) ws[wid] = incl;
    __syncthreads();
    int base = 0;
    for (int w = 0; w < wid; w++) base += ws[w];
    int excl = base + incl - v;
    if (t < NB) g_boff[t] = excl;
    if (t == NB - 1) g_rowptr[NN] = excl + v;
    // zero the dummy row NN of all fp16 tables (pads gather from here)
    if (t == 100) {
        uint4 z = make_uint4(0u, 0u, 0u, 0u);
        g_y0h[NN * 2] = z; g_y0h[NN * 2 + 1] = z;
        g_yA[NN * 2]  = z; g_yA[NN * 2 + 1]  = z;
        g_yB[NN * 2]  = z; g_yB[NN * 2 + 1]  = z;
    }
}

__global__ __launch_bounds__(1024) void writeout_kernel() {
    int b = blockIdx.x;
    int t = threadIdx.x;
    int i = b * 1024 + t;
    int vr = (i < NN) ? g_deg[i] : 0;
    int v = (vr + 3) & ~3;                 // padded degree
    int lane = t & 31, wid = t >> 5;
    int incl = v;
#pragma unroll
    for (int off = 1; off < 32; off <<= 1) {
        int n = __shfl_up_sync(0xffffffffu, incl, off);
        if (lane >= off) incl += n;
    }
    __shared__ int ws[32];
    if (lane == 31) ws[wid] = incl;
    __syncthreads();
    if (t < 32) {
        int s = ws[t];
#pragma unroll
        for (int off = 1; off < 32; off <<= 1) {
            int n = __shfl_up_sync(0xffffffffu, s, off);
            if (lane >= off) s += n;
        }
        ws[t] = s;
    }
    __syncthreads();
    int warpbase = (wid > 0) ? ws[wid - 1] : 0;
    int excl = g_boff[b] + warpbase + incl - v;
    if (i < NN) {
        g_rowptr[i] = excl;
        g_next[i] = excl;
        int* src = (int*)g_src4;
        for (int j = vr; j < v; j++) src[excl + j] = NN;   // pad slots
    }
}

__global__ void scatter_kernel(const int* __restrict__ row,
                               const int* __restrict__ col) {
    int e = blockIdx.x * blockDim.x + threadIdx.x;
    if (e >= EE) return;
    int c = col[e];
    int pos = atomicAdd(&g_next[c], 1);
    ((int*)g_src4)[pos] = row[e];
}

// =====================================================================
// MLP: y0 = dinv .* ( relu(x@W1 + b1) @ W2 + b2 )
// via mma.sync m16n8k16 FP16, SINGLE product: A = fp16(x), B = fp16(W1)
// (error budget empirically calibrated: each fp16 operand table adds
//  ~4e-5 to the final norm-relative error; total ~6.5e-5 vs 1e-3 gate)
// x staging register-pipelined (chunk c+1 prefetched during chunk c MMAs).
// =====================================================================
#define KCH 64
#define AF_HI 0u          // 8 stripes * 4 ksteps * 32 lanes * 16B = 16384
#define BF_HI 16384u      // 8 ntiles  * 4 ksteps * 32 lanes *  8B = 8192
#define W2_OFF 33280u     // after hid tile (128*65*4 = 33280)
#define B1_OFF 37376u
#define B2_OFF 37632u
#define SMEM_TOT 37696
#define HID_STRIDE 65

__device__ __forceinline__ uint32_t pack_h2(float a, float b) {
    __half2 h = __floats2half2_rn(a, b);
    return *reinterpret_cast<uint32_t*>(&h);
}

__device__ __forceinline__ void mma16816(float* c, const uint32_t* a, uint32_t b0, uint32_t b1) {
    asm volatile(
        "mma.sync.aligned.m16n8k16.row.col.f32.f16.f16.f32 "
        "{%0,%1,%2,%3}, {%4,%5,%6,%7}, {%8,%9}, {%0,%1,%2,%3};"
        : "+f"(c[0]), "+f"(c[1]), "+f"(c[2]), "+f"(c[3])
        : "r"(a[0]), "r"(a[1]), "r"(a[2]), "r"(a[3]), "r"(b0), "r"(b1));
}

__global__ __launch_bounds__(256, 2)
void mlp_mma_kernel(const float* __restrict__ x,
                    const float* __restrict__ W1,
                    const float* __restrict__ b1,
                    const float* __restrict__ W2,
                    const float* __restrict__ b2) {
    extern __shared__ char smem[];
    int tid = threadIdx.x;
    int wid = tid >> 5;
    int lane = tid & 31;
    int rowBase = blockIdx.x * 128;

    *(float4*)(smem + W2_OFF + tid * 16) = *(const float4*)&W2[tid * 4];
    if (tid < HC) *(float*)(smem + B1_OFF + tid * 4) = b1[tid];
    if (tid < OC) *(float*)(smem + B2_OFF + tid * 4) = b2[tid];

    uint32_t* afh = (uint32_t*)(smem + AF_HI);
    uint32_t* bfh = (uint32_t*)(smem + BF_HI);

    float acc[8][4];
#pragma unroll
    for (int nt = 0; nt < 8; nt++)
#pragma unroll
        for (int j = 0; j < 4; j++) acc[nt][j] = 0.f;

    float4 xs[8];
#define LOAD_CHUNK(cc) do {                                                 \
        int kcL = (cc) * KCH;                                               \
        _Pragma("unroll")                                                   \
        for (int i = 0; i < 8; i++) {                                       \
            int idx = i * 256 + tid;                                        \
            int row = idx >> 4;                                             \
            int kq = (idx & 15) * 4;                                        \
            int grow = rowBase + row;                                       \
            int gk = kcL + kq;                                              \
            xs[i] = make_float4(0.f, 0.f, 0.f, 0.f);                        \
            if (grow < NN && gk < IC) xs[i] = *(const float4*)&x[grow * IC + gk]; \
        }                                                                   \
    } while (0)

    LOAD_CHUNK(0);

    for (int c = 0; c < 8; c++) {
        int kc = c * KCH;
        __syncthreads();

        // ---- stage A from registers (single fp16 table, frag layout) ----
#pragma unroll
        for (int i = 0; i < 8; i++) {
            int idx = i * 256 + tid;
            int row = idx >> 4;
            int kq = (idx & 15) * 4;
            float4 xv = xs[i];
            uint32_t h0 = pack_h2(xv.x, xv.y);
            uint32_t h1 = pack_h2(xv.z, xv.w);
            int w = row >> 4;
            {
                int kl = kq;
                int s = kl >> 4;
                int ln = ((row & 7) << 2) | ((kl >> 1) & 3);
                int comp = ((kl & 15) >= 8 ? 2 : 0) + ((row & 15) >= 8 ? 1 : 0);
                afh[((w * 4 + s) * 32 + ln) * 4 + comp] = h0;
            }
            {
                int kl = kq + 2;
                int s = kl >> 4;
                int ln = ((row & 7) << 2) | ((kl >> 1) & 3);
                int comp = ((kl & 15) >= 8 ? 2 : 0) + ((row & 15) >= 8 ? 1 : 0);
                afh[((w * 4 + s) * 32 + ln) * 4 + comp] = h1;
            }
        }
        if (c < 7) LOAD_CHUNK(c + 1);

        // ---- stage B: fp16(W1^T), single table ----
        {
            int n = tid & 63;
            int kb = (tid >> 6) * 16;
            int nt = n >> 3;
            int lnbase = (n & 7) << 2;
#pragma unroll
            for (int i = 0; i < 8; i++) {
                int kl = kb + 2 * i;
                int gk0 = kc + kl;
                float w0 = (gk0 < IC) ? W1[gk0 * HC + n] : 0.f;
                float w1 = (gk0 + 1 < IC) ? W1[(gk0 + 1) * HC + n] : 0.f;
                uint32_t h = pack_h2(w0, w1);
                int s = kl >> 4;
                int ln = lnbase | ((kl >> 1) & 3);
                int comp = (kl & 15) >= 8 ? 1 : 0;
                bfh[((nt * 4 + s) * 32 + ln) * 2 + comp] = h;
            }
        }
        __syncthreads();

        const uint4* afh4 = (const uint4*)(smem + AF_HI);
        const uint2* bfh2 = (const uint2*)(smem + BF_HI);
#pragma unroll
        for (int s = 0; s < 4; s++) {
            uint4 ah4 = afh4[(wid * 4 + s) * 32 + lane];
            uint32_t ah[4] = {ah4.x, ah4.y, ah4.z, ah4.w};
#pragma unroll
            for (int nt = 0; nt < 8; nt++) {
                uint2 bh = bfh2[(nt * 4 + s) * 32 + lane];
                mma16816(acc[nt], ah, bh.x, bh.y);
            }
        }
    }
#undef LOAD_CHUNK

    __syncthreads();
    {
        float* hid = (float*)smem;
        const float* b1s = (const float*)(smem + B1_OFF);
        int r0 = wid * 16 + (lane >> 2);
        int c0 = (lane & 3) * 2;
#pragma unroll
        for (int nt = 0; nt < 8; nt++) {
            int col = nt * 8 + c0;
            float bcol0 = b1s[col];
            float bcol1 = b1s[col + 1];
            hid[r0 * HID_STRIDE + col]           = fmaxf(acc[nt][0] + bcol0, 0.f);
            hid[r0 * HID_STRIDE + col + 1]       = fmaxf(acc[nt][1] + bcol1, 0.f);
            hid[(r0 + 8) * HID_STRIDE + col]     = fmaxf(acc[nt][2] + bcol0, 0.f);
            hid[(r0 + 8) * HID_STRIDE + col + 1] = fmaxf(acc[nt][3] + bcol1, 0.f);
        }
    }
    __syncthreads();

    if (tid < 128) {
        const float* hid = (const float*)smem;
        const float* b2s = (const float*)(smem + B2_OFF);
        const float4* w2s = (const float4*)(smem + W2_OFF);
        const float* hrow = &hid[tid * HID_STRIDE];

        float4 o0 = make_float4(b2s[0], b2s[1], b2s[2], b2s[3]);
        float4 o1 = make_float4(b2s[4], b2s[5], b2s[6], b2s[7]);
        float4 o2 = make_float4(b2s[8], b2s[9], b2s[10], b2s[11]);
        float4 o3 = make_float4(b2s[12], b2s[13], b2s[14], b2s[15]);
#pragma unroll
        for (int k = 0; k < HC; k++) {
            float h = hrow[k];
            float4 wa = w2s[k * 4 + 0];
            float4 wb = w2s[k * 4 + 1];
            float4 wc = w2s[k * 4 + 2];
            float4 wd = w2s[k * 4 + 3];
            o0.x = fmaf(h, wa.x, o0.x); o0.y = fmaf(h, wa.y, o0.y);
            o0.z = fmaf(h, wa.z, o0.z); o0.w = fmaf(h, wa.w, o0.w);
            o1.x = fmaf(h, wb.x, o1.x); o1.y = fmaf(h, wb.y, o1.y);
            o1.z = fmaf(h, wb.z, o1.z); o1.w = fmaf(h, wb.w, o1.w);
            o2.x = fmaf(h, wc.x, o2.x); o2.y = fmaf(h, wc.y, o2.y);
            o2.z = fmaf(h, wc.z, o2.z); o2.w = fmaf(h, wc.w, o2.w);
            o3.x = fmaf(h, wd.x, o3.x); o3.y = fmaf(h, wd.y, o3.y);
            o3.z = fmaf(h, wd.z, o3.z); o3.w = fmaf(h, wd.w, o3.w);
        }
        int grow = rowBase + tid;
        if (grow < NN) {
            float di = g_dinv[grow];   // y0 = dinv * h0
            o0.x *= di; o0.y *= di; o0.z *= di; o0.w *= di;
            o1.x *= di; o1.y *= di; o1.z *= di; o1.w *= di;
            o2.x *= di; o2.y *= di; o2.z *= di; o2.w *= di;
            o3.x *= di; o3.y *= di; o3.z *= di; o3.w *= di;
            g_h0[grow * 4 + 0] = o0;
            g_h0[grow * 4 + 1] = o1;
            g_h0[grow * 4 + 2] = o2;
            g_h0[grow * 4 + 3] = o3;
            uint4 p0, p1;
            p0.x = pack_h2(o0.x, o0.y); p0.y = pack_h2(o0.z, o0.w);
            p0.z = pack_h2(o1.x, o1.y); p0.w = pack_h2(o1.z, o1.w);
            p1.x = pack_h2(o2.x, o2.y); p1.y = pack_h2(o2.z, o2.w);
            p1.z = pack_h2(o3.x, o3.y); p1.w = pack_h2(o3.z, o3.w);
            g_y0h[grow * 2 + 0] = p0;
            g_y0h[grow * 2 + 1] = p1;
        }
    }
}

// ---------------- APPNP propagation: 2 lanes per node, zero shuffles ----------------
// intermediate: y_{k+1} = 0.9*dinv^2*(sum_in y + y_self) + 0.1*y0   (fp16 store)
// final:        out     = 0.9*dinv  *(sum_in y + y_self) + 0.1*y0/dinv (fp32)
__global__ __launch_bounds__(256) void prop_kernel(int insel, int outsel,
                                                   float4* __restrict__ dout) {
    const uint4* yin = (insel == 0) ? g_y0h : ((insel == 1) ? g_yA : g_yB);
    uint4* yout = (outsel == 1) ? g_yA : g_yB;
    bool final_step = (outsel == 3);

    int t = blockIdx.x * blockDim.x + threadIdx.x;
    int node = t >> 1;
    if (node >= NN) return;
    int hf = t & 1;                  // 16B half of the 32B fp16 row

    int start = g_rowptr[node];
    int end = g_rowptr[node + 1];    // padded: (end-start) % 4 == 0

    float a0 = 0.f, a1 = 0.f, a2 = 0.f, a3 = 0.f;
    float a4 = 0.f, a5 = 0.f, a6 = 0.f, a7 = 0.f;

#define GATHER(id) do {                                              \
        uint4 v = yin[(id) * 2 + hf];                                \
        float2 f0 = __half22float2(*reinterpret_cast<__half2*>(&v.x)); \
        float2 f1 = __half22float2(*reinterpret_cast<__half2*>(&v.y)); \
        float2 f2 = __half22float2(*reinterpret_cast<__half2*>(&v.z)); \
        float2 f3 = __half22float2(*reinterpret_cast<__half2*>(&v.w)); \
        a0 += f0.x; a1 += f0.y; a2 += f1.x; a3 += f1.y;              \
        a4 += f2.x; a5 += f2.y; a6 += f3.x; a7 += f3.y;              \
    } while (0)

    for (int e = start; e < end; e += 4) {
        int4 ids = g_src4[e >> 2];    // broadcast within the lane pair
        GATHER(ids.x);
        GATHER(ids.y);
        GATHER(ids.z);
        GATHER(ids.w);
    }
#undef GATHER

    // self term (fp16 table)
    {
        uint4 s = yin[node * 2 + hf];
        float2 s0 = __half22float2(*reinterpret_cast<__half2*>(&s.x));
        float2 s1 = __half22float2(*reinterpret_cast<__half2*>(&s.y));
        float2 s2 = __half22float2(*reinterpret_cast<__half2*>(&s.z));
        float2 s3 = __half22float2(*reinterpret_cast<__half2*>(&s.w));
        a0 += s0.x; a1 += s0.y; a2 += s1.x; a3 += s1.y;
        a4 += s2.x; a5 += s2.y; a6 += s3.x; a7 += s3.y;
    }

    float di = g_dinv[node];
    float4 y0a = g_h0[node * 4 + hf * 2];      // fp32 anchor
    float4 y0b = g_h0[node * 4 + hf * 2 + 1];
    if (!final_step) {
        float d2 = 0.9f * di * di;
        float o0 = d2 * a0 + 0.1f * y0a.x;
        float o1 = d2 * a1 + 0.1f * y0a.y;
        float o2 = d2 * a2 + 0.1f * y0a.z;
        float o3 = d2 * a3 + 0.1f * y0a.w;
        float o4 = d2 * a4 + 0.1f * y0b.x;
        float o5 = d2 * a5 + 0.1f * y0b.y;
        float o6 = d2 * a6 + 0.1f * y0b.z;
        float o7 = d2 * a7 + 0.1f * y0b.w;
        uint4 p;
        p.x = pack_h2(o0, o1); p.y = pack_h2(o2, o3);
        p.z = pack_h2(o4, o5); p.w = pack_h2(o6, o7);
        yout[node * 2 + hf] = p;
    } else {
        float dm = 0.9f * di;
        float inv = 0.1f / di;
        float4 oa, ob;
        oa.x = dm * a0 + inv * y0a.x;
        oa.y = dm * a1 + inv * y0a.y;
        oa.z = dm * a2 + inv * y0a.z;
        oa.w = dm * a3 + inv * y0a.w;
        ob.x = dm * a4 + inv * y0b.x;
        ob.y = dm * a5 + inv * y0b.y;
        ob.z = dm * a6 + inv * y0b.z;
        ob.w = dm * a7 + inv * y0b.w;
        dout[node * 4 + hf * 2] = oa;
        dout[node * 4 + hf * 2 + 1] = ob;
    }
}

// ---------------- launch ----------------
extern "C" void kernel_launch(void* const* d_in, const int* in_sizes, int n_in,
                              void* d_out, int out_size) {
    const float* x  = (const float*)d_in[0];
    const int* ei   = (const int*)d_in[1];   // int32 (JAX x64-disabled)
    const float* W1 = (const float*)d_in[2];
    const float* b1 = (const float*)d_in[3];
    const float* W2 = (const float*)d_in[4];
    const float* b2 = (const float*)d_in[5];
    float4* out = (float4*)d_out;

    const int* row = ei;        // sources
    const int* col = ei + EE;   // targets

    zero_deg_kernel<<<(NN + 255) / 256, 256>>>();
    hist_kernel<<<(EE + 255) / 256, 256>>>(col);
    reduce_kernel<<<NB, 1024>>>();           // dinv + padded-degree partial sums
    scanb_kernel<<<1, 128>>>();              // + zero dummy rows
    writeout_kernel<<<NB, 1024>>>();         // rowptr/next + pad fill
    scatter_kernel<<<(EE + 255) / 256, 256>>>(row, col);

    cudaFuncSetAttribute(mlp_mma_kernel, cudaFuncAttributeMaxDynamicSharedMemorySize, SMEM_TOT);
    mlp_mma_kernel<<<(NN + 127) / 128, 256, SMEM_TOT>>>(x, W1, b1, W2, b2);

    int insel = 0;
    for (int k = 0; k < 10; k++) {
        int outsel = (k == 9) ? 3 : ((k & 1) ? 2 : 1);
        prop_kernel<<<(NN * 2 + 255) / 256, 256>>>(insel, outsel, out);
        insel = outsel;
    }
}

// round 17
// speedup vs baseline: 1.3299x; 1.0008x over previous
#include <cuda_runtime.h>
#include <cuda_bf16.h>
#include <cuda_fp16.h>
#include <cstdint>

#define NN 100000
#define EE 3200000
#define IC 500
#define HC 64
#define OC 16
#define NB 98            // scan blocks: 98*1024 >= NN (all co-resident: no deadlock)
#define SRC4_CAP 880000  // >= (EE + 3*NN)/4

// ---------------- scratch (device globals; no allocation allowed) ----------------
__device__ float4 g_h0[NN * 4];          // y0 = dinv .* h0  (fp32 anchor, exact)
__device__ uint4  g_y0h[(NN + 1) * 2];   // y0 fp16 table (+ zero row NN)
__device__ uint4  g_yA[(NN + 1) * 2];    // fp16 ping
__device__ uint4  g_yB[(NN + 1) * 2];    // fp16 pong
__device__ float  g_dinv[NN];
__device__ int    g_deg[NN];             // zero-init at load; re-zeroed by scan each run
__device__ int    g_rowptr[NN + 1];      // padded (deg rounded up to 4)
__device__ int    g_next[NN];
__device__ int4   g_src4[SRC4_CAP];      // CSR src ids, 4-aligned rows, pads = NN
__device__ unsigned long long g_sstate[NB];  // lookback state; re-zeroed by scatter

// ---------------- graph preprocessing ----------------
__global__ void hist_kernel(const int* __restrict__ col) {
    int e = blockIdx.x * blockDim.x + threadIdx.x;
    if (e < EE) atomicAdd(&g_deg[col[e]], 1);
}

// Fused: dinv + single-pass decoupled-lookback scan of padded degrees +
// rowptr/cursor/pad writeout + g_deg self-clean + dummy-row zeroing.
__global__ __launch_bounds__(1024) void scanfused_kernel() {
    int b = blockIdx.x;
    int t = threadIdx.x;
    int i = b * 1024 + t;
    int vr = (i < NN) ? g_deg[i] : 0;
    if (i < NN) {
        g_dinv[i] = rsqrtf((float)(vr + 1));  // +1 self-loop
        g_deg[i] = 0;                          // self-clean for next run
    }
    int v = (vr + 3) & ~3;                     // padded degree

    // block-local inclusive scan
    int lane = t & 31, wid = t >> 5;
    int incl = v;
#pragma unroll
    for (int off = 1; off < 32; off <<= 1) {
        int n = __shfl_up_sync(0xffffffffu, incl, off);
        if (lane >= off) incl += n;
    }
    __shared__ int ws[32];
    if (lane == 31) ws[wid] = incl;
    __syncthreads();
    if (t < 32) {
        int s = ws[t];
#pragma unroll
        for (int off = 1; off < 32; off <<= 1) {
            int n = __shfl_up_sync(0xffffffffu, s, off);
            if (lane >= off) s += n;
        }
        ws[t] = s;
    }
    __syncthreads();
    int warpbase = (wid > 0) ? ws[wid - 1] : 0;
    int total = ws[31];

    // decoupled lookback (thread 0): state = (value<<2)|flag, flag 1=aggregate 2=prefix
    __shared__ int s_prefix;
    if (t == 0) {
        atomicExch(&g_sstate[b], ((unsigned long long)(unsigned)total << 2) | 1ull);
        long long run = 0;
        for (int p = b - 1; p >= 0; p--) {
            unsigned long long s;
            do { s = atomicAdd(&g_sstate[p], 0ull); } while ((s & 3ull) == 0ull);
            run += (long long)(s >> 2);
            if ((s & 3ull) == 2ull) break;
        }
        s_prefix = (int)run;
        atomicExch(&g_sstate[b],
                   ((unsigned long long)(unsigned)(run + total) << 2) | 2ull);
    }
    __syncthreads();

    int excl = s_prefix + warpbase + incl - v;
    if (i < NN) {
        g_rowptr[i] = excl;
        g_next[i] = excl;
        int* src = (int*)g_src4;
        for (int j = vr; j < v; j++) src[excl + j] = NN;   // pad slots
    }
    if (b == NB - 1 && t == 1023) g_rowptr[NN] = s_prefix + total;
    // zero the dummy row NN of all fp16 tables (idempotent; never written elsewhere)
    if (b == 0 && t == 100) {
        uint4 z = make_uint4(0u, 0u, 0u, 0u);
        g_y0h[NN * 2] = z; g_y0h[NN * 2 + 1] = z;
        g_yA[NN * 2]  = z; g_yA[NN * 2 + 1]  = z;
        g_yB[NN * 2]  = z; g_yB[NN * 2 + 1]  = z;
    }
}

__global__ void scatter_kernel(const int* __restrict__ row,
                               const int* __restrict__ col) {
    // re-zero the lookback state for the next run (scan is fully done by now)
    if (blockIdx.x == 0 && threadIdx.x < NB) g_sstate[threadIdx.x] = 0ull;
    int e = blockIdx.x * blockDim.x + threadIdx.x;
    if (e >= EE) return;
    int c = col[e];
    int pos = atomicAdd(&g_next[c], 1);
    ((int*)g_src4)[pos] = row[e];
}

// =====================================================================
// MLP: y0 = dinv .* ( relu(x@W1 + b1) @ W2 + b2 )
// via mma.sync m16n8k16 FP16, single product (calibrated err ~6e-5)
// x staging register-pipelined.
// =====================================================================
#define KCH 64
#define AF_HI 0u          // 8 stripes * 4 ksteps * 32 lanes * 16B = 16384
#define BF_HI 16384u      // 8 ntiles  * 4 ksteps * 32 lanes *  8B = 8192
#define W2_OFF 33280u     // after hid tile (128*65*4 = 33280)
#define B1_OFF 37376u
#define B2_OFF 37632u
#define SMEM_TOT 37696
#define HID_STRIDE 65

__device__ __forceinline__ uint32_t pack_h2(float a, float b) {
    __half2 h = __floats2half2_rn(a, b);
    return *reinterpret_cast<uint32_t*>(&h);
}

__device__ __forceinline__ void mma16816(float* c, const uint32_t* a, uint32_t b0, uint32_t b1) {
    asm volatile(
        "mma.sync.aligned.m16n8k16.row.col.f32.f16.f16.f32 "
        "{%0,%1,%2,%3}, {%4,%5,%6,%7}, {%8,%9}, {%0,%1,%2,%3};"
        : "+f"(c[0]), "+f"(c[1]), "+f"(c[2]), "+f"(c[3])
        : "r"(a[0]), "r"(a[1]), "r"(a[2]), "r"(a[3]), "r"(b0), "r"(b1));
}

__global__ __launch_bounds__(256, 2)
void mlp_mma_kernel(const float* __restrict__ x,
                    const float* __restrict__ W1,
                    const float* __restrict__ b1,
                    const float* __restrict__ W2,
                    const float* __restrict__ b2) {
    extern __shared__ char smem[];
    int tid = threadIdx.x;
    int wid = tid >> 5;
    int lane = tid & 31;
    int rowBase = blockIdx.x * 128;

    *(float4*)(smem + W2_OFF + tid * 16) = *(const float4*)&W2[tid * 4];
    if (tid < HC) *(float*)(smem + B1_OFF + tid * 4) = b1[tid];
    if (tid < OC) *(float*)(smem + B2_OFF + tid * 4) = b2[tid];

    uint32_t* afh = (uint32_t*)(smem + AF_HI);
    uint32_t* bfh = (uint32_t*)(smem + BF_HI);

    float acc[8][4];
#pragma unroll
    for (int nt = 0; nt < 8; nt++)
#pragma unroll
        for (int j = 0; j < 4; j++) acc[nt][j] = 0.f;

    float4 xs[8];
#define LOAD_CHUNK(cc) do {                                                 \
        int kcL = (cc) * KCH;                                               \
        _Pragma("unroll")                                                   \
        for (int i = 0; i < 8; i++) {                                       \
            int idx = i * 256 + tid;                                        \
            int row = idx >> 4;                                             \
            int kq = (idx & 15) * 4;                                        \
            int grow = rowBase + row;                                       \
            int gk = kcL + kq;                                              \
            xs[i] = make_float4(0.f, 0.f, 0.f, 0.f);                        \
            if (grow < NN && gk < IC) xs[i] = *(const float4*)&x[grow * IC + gk]; \
        }                                                                   \
    } while (0)

    LOAD_CHUNK(0);

    for (int c = 0; c < 8; c++) {
        int kc = c * KCH;
        __syncthreads();

        // ---- stage A from registers (single fp16 table, frag layout) ----
#pragma unroll
        for (int i = 0; i < 8; i++) {
            int idx = i * 256 + tid;
            int row = idx >> 4;
            int kq = (idx & 15) * 4;
            float4 xv = xs[i];
            uint32_t h0 = pack_h2(xv.x, xv.y);
            uint32_t h1 = pack_h2(xv.z, xv.w);
            int w = row >> 4;
            {
                int kl = kq;
                int s = kl >> 4;
                int ln = ((row & 7) << 2) | ((kl >> 1) & 3);
                int comp = ((kl & 15) >= 8 ? 2 : 0) + ((row & 15) >= 8 ? 1 : 0);
                afh[((w * 4 + s) * 32 + ln) * 4 + comp] = h0;
            }
            {
                int kl = kq + 2;
                int s = kl >> 4;
                int ln = ((row & 7) << 2) | ((kl >> 1) & 3);
                int comp = ((kl & 15) >= 8 ? 2 : 0) + ((row & 15) >= 8 ? 1 : 0);
                afh[((w * 4 + s) * 32 + ln) * 4 + comp] = h1;
            }
        }
        if (c < 7) LOAD_CHUNK(c + 1);

        // ---- stage B: fp16(W1^T), single table ----
        {
            int n = tid & 63;
            int kb = (tid >> 6) * 16;
            int nt = n >> 3;
            int lnbase = (n & 7) << 2;
#pragma unroll
            for (int i = 0; i < 8; i++) {
                int kl = kb + 2 * i;
                int gk0 = kc + kl;
                float w0 = (gk0 < IC) ? W1[gk0 * HC + n] : 0.f;
                float w1 = (gk0 + 1 < IC) ? W1[(gk0 + 1) * HC + n] : 0.f;
                uint32_t h = pack_h2(w0, w1);
                int s = kl >> 4;
                int ln = lnbase | ((kl >> 1) & 3);
                int comp = (kl & 15) >= 8 ? 1 : 0;
                bfh[((nt * 4 + s) * 32 + ln) * 2 + comp] = h;
            }
        }
        __syncthreads();

        const uint4* afh4 = (const uint4*)(smem + AF_HI);
        const uint2* bfh2 = (const uint2*)(smem + BF_HI);
#pragma unroll
        for (int s = 0; s < 4; s++) {
            uint4 ah4 = afh4[(wid * 4 + s) * 32 + lane];
            uint32_t ah[4] = {ah4.x, ah4.y, ah4.z, ah4.w};
#pragma unroll
            for (int nt = 0; nt < 8; nt++) {
                uint2 bh = bfh2[(nt * 4 + s) * 32 + lane];
                mma16816(acc[nt], ah, bh.x, bh.y);
            }
        }
    }
#undef LOAD_CHUNK

    __syncthreads();
    {
        float* hid = (float*)smem;
        const float* b1s = (const float*)(smem + B1_OFF);
        int r0 = wid * 16 + (lane >> 2);
        int c0 = (lane & 3) * 2;
#pragma unroll
        for (int nt = 0; nt < 8; nt++) {
            int col = nt * 8 + c0;
            float bcol0 = b1s[col];
            float bcol1 = b1s[col + 1];
            hid[r0 * HID_STRIDE + col]           = fmaxf(acc[nt][0] + bcol0, 0.f);
            hid[r0 * HID_STRIDE + col + 1]       = fmaxf(acc[nt][1] + bcol1, 0.f);
            hid[(r0 + 8) * HID_STRIDE + col]     = fmaxf(acc[nt][2] + bcol0, 0.f);
            hid[(r0 + 8) * HID_STRIDE + col + 1] = fmaxf(acc[nt][3] + bcol1, 0.f);
        }
    }
    __syncthreads();

    if (tid < 128) {
        const float* hid = (const float*)smem;
        const float* b2s = (const float*)(smem + B2_OFF);
        const float4* w2s = (const float4*)(smem + W2_OFF);
        const float* hrow = &hid[tid * HID_STRIDE];

        float4 o0 = make_float4(b2s[0], b2s[1], b2s[2], b2s[3]);
        float4 o1 = make_float4(b2s[4], b2s[5], b2s[6], b2s[7]);
        float4 o2 = make_float4(b2s[8], b2s[9], b2s[10], b2s[11]);
        float4 o3 = make_float4(b2s[12], b2s[13], b2s[14], b2s[15]);
#pragma unroll
        for (int k = 0; k < HC; k++) {
            float h = hrow[k];
            float4 wa = w2s[k * 4 + 0];
            float4 wb = w2s[k * 4 + 1];
            float4 wc = w2s[k * 4 + 2];
            float4 wd = w2s[k * 4 + 3];
            o0.x = fmaf(h, wa.x, o0.x); o0.y = fmaf(h, wa.y, o0.y);
            o0.z = fmaf(h, wa.z, o0.z); o0.w = fmaf(h, wa.w, o0.w);
            o1.x = fmaf(h, wb.x, o1.x); o1.y = fmaf(h, wb.y, o1.y);
            o1.z = fmaf(h, wb.z, o1.z); o1.w = fmaf(h, wb.w, o1.w);
            o2.x = fmaf(h, wc.x, o2.x); o2.y = fmaf(h, wc.y, o2.y);
            o2.z = fmaf(h, wc.z, o2.z); o2.w = fmaf(h, wc.w, o2.w);
            o3.x = fmaf(h, wd.x, o3.x); o3.y = fmaf(h, wd.y, o3.y);
            o3.z = fmaf(h, wd.z, o3.z); o3.w = fmaf(h, wd.w, o3.w);
        }
        int grow = rowBase + tid;
        if (grow < NN) {
            float di = g_dinv[grow];   // y0 = dinv * h0
            o0.x *= di; o0.y *= di; o0.z *= di; o0.w *= di;
            o1.x *= di; o1.y *= di; o1.z *= di; o1.w *= di;
            o2.x *= di; o2.y *= di; o2.z *= di; o2.w *= di;
            o3.x *= di; o3.y *= di; o3.z *= di; o3.w *= di;
            g_h0[grow * 4 + 0] = o0;
            g_h0[grow * 4 + 1] = o1;
            g_h0[grow * 4 + 2] = o2;
            g_h0[grow * 4 + 3] = o3;
            uint4 p0, p1;
            p0.x = pack_h2(o0.x, o0.y); p0.y = pack_h2(o0.z, o0.w);
            p0.z = pack_h2(o1.x, o1.y); p0.w = pack_h2(o1.z, o1.w);
            p1.x = pack_h2(o2.x, o2.y); p1.y = pack_h2(o2.z, o2.w);
            p1.z = pack_h2(o3.x, o3.y); p1.w = pack_h2(o3.z, o3.w);
            g_y0h[grow * 2 + 0] = p0;
            g_y0h[grow * 2 + 1] = p1;
        }
    }
}

// ---------------- APPNP propagation: 2 lanes per node, zero shuffles ----------------
// intermediate: y_{k+1} = 0.9*dinv^2*(sum_in y + y_self) + 0.1*y0   (fp16 store)
// final:        out     = 0.9*dinv  *(sum_in y + y_self) + 0.1*y0/dinv (fp32)
__global__ __launch_bounds__(256) void prop_kernel(int insel, int outsel,
                                                   float4* __restrict__ dout) {
    const uint4* yin = (insel == 0) ? g_y0h : ((insel == 1) ? g_yA : g_yB);
    uint4* yout = (outsel == 1) ? g_yA : g_yB;
    bool final_step = (outsel == 3);

    int t = blockIdx.x * blockDim.x + threadIdx.x;
    int node = t >> 1;
    if (node >= NN) return;
    int hf = t & 1;                  // 16B half of the 32B fp16 row

    int start = g_rowptr[node];
    int end = g_rowptr[node + 1];    // padded: (end-start) % 4 == 0

    float a0 = 0.f, a1 = 0.f, a2 = 0.f, a3 = 0.f;
    float a4 = 0.f, a5 = 0.f, a6 = 0.f, a7 = 0.f;

#define GATHER(id) do {                                              \
        uint4 v = yin[(id) * 2 + hf];                                \
        float2 f0 = __half22float2(*reinterpret_cast<__half2*>(&v.x)); \
        float2 f1 = __half22float2(*reinterpret_cast<__half2*>(&v.y)); \
        float2 f2 = __half22float2(*reinterpret_cast<__half2*>(&v.z)); \
        float2 f3 = __half22float2(*reinterpret_cast<__half2*>(&v.w)); \
        a0 += f0.x; a1 += f0.y; a2 += f1.x; a3 += f1.y;              \
        a4 += f2.x; a5 += f2.y; a6 += f3.x; a7 += f3.y;              \
    } while (0)

    for (int e = start; e < end; e += 4) {
        int4 ids = g_src4[e >> 2];    // broadcast within the lane pair
        GATHER(ids.x);
        GATHER(ids.y);
        GATHER(ids.z);
        GATHER(ids.w);
    }
#undef GATHER

    // self term (fp16 table)
    {
        uint4 s = yin[node * 2 + hf];
        float2 s0 = __half22float2(*reinterpret_cast<__half2*>(&s.x));
        float2 s1 = __half22float2(*reinterpret_cast<__half2*>(&s.y));
        float2 s2 = __half22float2(*reinterpret_cast<__half2*>(&s.z));
        float2 s3 = __half22float2(*reinterpret_cast<__half2*>(&s.w));
        a0 += s0.x; a1 += s0.y; a2 += s1.x; a3 += s1.y;
        a4 += s2.x; a5 += s2.y; a6 += s3.x; a7 += s3.y;
    }

    float di = g_dinv[node];
    float4 y0a = g_h0[node * 4 + hf * 2];      // fp32 anchor
    float4 y0b = g_h0[node * 4 + hf * 2 + 1];
    if (!final_step) {
        float d2 = 0.9f * di * di;
        float o0 = d2 * a0 + 0.1f * y0a.x;
        float o1 = d2 * a1 + 0.1f * y0a.y;
        float o2 = d2 * a2 + 0.1f * y0a.z;
        float o3 = d2 * a3 + 0.1f * y0a.w;
        float o4 = d2 * a4 + 0.1f * y0b.x;
        float o5 = d2 * a5 + 0.1f * y0b.y;
        float o6 = d2 * a6 + 0.1f * y0b.z;
        float o7 = d2 * a7 + 0.1f * y0b.w;
        uint4 p;
        p.x = pack_h2(o0, o1); p.y = pack_h2(o2, o3);
        p.z = pack_h2(o4, o5); p.w = pack_h2(o6, o7);
        yout[node * 2 + hf] = p;
    } else {
        float dm = 0.9f * di;
        float inv = 0.1f / di;
        float4 oa, ob;
        oa.x = dm * a0 + inv * y0a.x;
        oa.y = dm * a1 + inv * y0a.y;
        oa.z = dm * a2 + inv * y0a.z;
        oa.w = dm * a3 + inv * y0a.w;
        ob.x = dm * a4 + inv * y0b.x;
        ob.y = dm * a5 + inv * y0b.y;
        ob.z = dm * a6 + inv * y0b.z;
        ob.w = dm * a7 + inv * y0b.w;
        dout[node * 4 + hf * 2] = oa;
        dout[node * 4 + hf * 2 + 1] = ob;
    }
}

// ---------------- launch ----------------
extern "C" void kernel_launch(void* const* d_in, const int* in_sizes, int n_in,
                              void* d_out, int out_size) {
    const float* x  = (const float*)d_in[0];
    const int* ei   = (const int*)d_in[1];   // int32 (JAX x64-disabled)
    const float* W1 = (const float*)d_in[2];
    const float* b1 = (const float*)d_in[3];
    const float* W2 = (const float*)d_in[4];
    const float* b2 = (const float*)d_in[5];
    float4* out = (float4*)d_out;

    const int* row = ei;        // sources
    const int* col = ei + EE;   // targets

    hist_kernel<<<(EE + 255) / 256, 256>>>(col);           // g_deg pre-zeroed (self-clean)
    scanfused_kernel<<<NB, 1024>>>();                      // dinv + scan + writeout + clean
    scatter_kernel<<<(EE + 255) / 256, 256>>>(row, col);   // + re-zero lookback state

    cudaFuncSetAttribute(mlp_mma_kernel, cudaFuncAttributeMaxDynamicSharedMemorySize, SMEM_TOT);
    mlp_mma_kernel<<<(NN + 127) / 128, 256, SMEM_TOT>>>(x, W1, b1, W2, b2);

    int insel = 0;
    for (int k = 0; k < 10; k++) {
        int outsel = (k == 9) ? 3 : ((k & 1) ? 2 : 1);
        prop_kernel<<<(NN * 2 + 255) / 256, 256>>>(insel, outsel, out);
        insel = outsel;
    }
}